// round 9
// baseline (speedup 1.0000x reference)
#include <cuda_runtime.h>

// Weighted MSE over predict/target [64, 3, 17, 4096] fp32.
//   w = {1, 1, 75825} per channel (dim 1), result = sum(w*(t-p)^2) / (64*17*4096)
//
// N float4 = 3,342,336 ; channel of float4 v = (v / 17408) % 3
//
// R9: mainloop is at the HBM roofline (7.22 TB/s = 90% of spec; R5/R7/R8 all
// identical). Remaining target = the serial reduction tail. Replace the
// last-block 888-float gmem reduce with a single u64 fixed-point atomicAdd:
// integer adds are order-independent -> bit-deterministic, and the last
// arriving thread0 just converts one value. No extra syncthreads, non-last
// blocks retire immediately after their atomic.

#define NVEC        3342336
#define VEC_PER_CH  17408
#define NBLOCKS     888                       // 148 * 6, one exact wave
#define NTHREADS    256
#define STRIDE      (NBLOCKS * NTHREADS)      // 227328
#define VPT         14                        // 14*STRIDE = 3182592
#define REM         (NVEC - VPT * STRIDE)     // 159744 (< STRIDE)
#define MAXLEN_W    75825.0f
#define INV_DENOM   (1.0 / 4456448.0)         // 1/(64*17*4096)
#define FP_SCALE    16384.0f                  // 2^14 fixed-point fraction
#define INV_SCALE   (1.0 / 16384.0)

__device__ unsigned long long g_total;        // zero-init; last block resets
__device__ unsigned int g_count;              // zero-init; last block resets

__device__ __forceinline__ float vec_term(const float4 a, const float4 b, const int v)
{
    const int ch = (v / VEC_PER_CH) % 3;
    const float w = (ch == 2) ? MAXLEN_W : 1.0f;
    const float d0 = b.x - a.x;
    const float d1 = b.y - a.y;
    const float d2 = b.z - a.z;
    const float d3 = b.w - a.w;
    return w * (d0 * d0 + d1 * d1 + d2 * d2 + d3 * d3);
}

__global__ __launch_bounds__(NTHREADS, 6) void mse_fused_kernel(
    const float4* __restrict__ predict,
    const float4* __restrict__ target,
    float* __restrict__ out)
{
    const int tid = blockIdx.x * NTHREADS + threadIdx.x;

    // 3-wide explicit load batch (6 LDG.128 in flight) + rotating accumulators.
    float s0 = 0.0f, s1 = 0.0f, s2 = 0.0f;
    int j = 0;
#pragma unroll
    for (; j + 3 <= VPT; j += 3) {            // 4 batches of 3 (12 vecs)
        const int v0 = tid + (j + 0) * STRIDE;
        const int v1 = tid + (j + 1) * STRIDE;
        const int v2 = tid + (j + 2) * STRIDE;
        const float4 a0 = predict[v0];
        const float4 b0 = target[v0];
        const float4 a1 = predict[v1];
        const float4 b1 = target[v1];
        const float4 a2 = predict[v2];
        const float4 b2 = target[v2];
        s0 += vec_term(a0, b0, v0);
        s1 += vec_term(a1, b1, v1);
        s2 += vec_term(a2, b2, v2);
    }
    {                                          // 2 leftover vecs (VPT%3 == 2)
        const int v0 = tid + (j + 0) * STRIDE;
        const int v1 = tid + (j + 1) * STRIDE;
        const float4 a0 = predict[v0];
        const float4 b0 = target[v0];
        const float4 a1 = predict[v1];
        const float4 b1 = target[v1];
        s0 += vec_term(a0, b0, v0);
        s1 += vec_term(a1, b1, v1);
    }
    if (tid < REM) {
        const int v = tid + VPT * STRIDE;
        s2 += vec_term(predict[v], target[v], v);
    }
    float s = s0 + s1 + s2;

    // block reduce
#pragma unroll
    for (int off = 16; off > 0; off >>= 1)
        s += __shfl_down_sync(0xFFFFFFFFu, s, off);

    __shared__ float smem[NTHREADS / 32];
    const int lane = threadIdx.x & 31;
    const int wid  = threadIdx.x >> 5;
    if (lane == 0) smem[wid] = s;
    __syncthreads();

    if (threadIdx.x == 0) {
        float bs = 0.0f;
#pragma unroll
        for (int i = 0; i < NTHREADS / 32; i++) bs += smem[i];

        // Deterministic accumulation: fixed-point u64 atomic (commutative,
        // order-independent -> bit-identical result every run).
        const unsigned long long q =
            (unsigned long long)(long long)llrintf(bs * FP_SCALE);
        atomicAdd(&g_total, q);
        __threadfence();
        const unsigned int old = atomicAdd(&g_count, 1u);
        if (old == NBLOCKS - 1) {
            // All blocks' totals are visible (each fenced before its count).
            const unsigned long long tot = atomicAdd(&g_total, 0ULL);
            out[0] = (float)((double)(long long)tot * INV_SCALE * INV_DENOM);
            g_total = 0ULL;   // reset for next graph replay
            g_count = 0u;
        }
    }
}

extern "C" void kernel_launch(void* const* d_in, const int* in_sizes, int n_in,
                              void* d_out, int out_size)
{
    const float4* predict = (const float4*)d_in[0];
    const float4* target  = (const float4*)d_in[1];
    float* out = (float*)d_out;

    mse_fused_kernel<<<NBLOCKS, NTHREADS>>>(predict, target, out);
}